// round 1
// baseline (speedup 1.0000x reference)
#include <cuda_runtime.h>
#include <cuda_bf16.h>

#define BB 4
#define CC 512
#define CI 256
#define NN 4096

// Scratch (device globals; no allocation allowed)
__device__ float g_theta[BB * CI * NN]; // [b][o][n]
__device__ float g_phi[BB * CI * NN];   // [b][o][n]
__device__ float g_g[BB * NN * CI];     // [b][n][o]
__device__ float g_y[BB * NN * CI];     // [b][n][o]

// ---------------------------------------------------------------------------
// Kernel 1: fused projections theta/phi/g.
// out[o,n] = sum_c W[o,c] * x[b,c,n] + bias[o]
// Tile 64o x 64n, k-chunk 16, 256 threads, 4x4 per thread.
// ---------------------------------------------------------------------------
__global__ __launch_bounds__(256) void proj_kernel(
    const float* __restrict__ x,
    const float* __restrict__ wt, const float* __restrict__ bt,
    const float* __restrict__ wp, const float* __restrict__ bp,
    const float* __restrict__ wg, const float* __restrict__ bg)
{
    int b  = blockIdx.z;
    int n0 = blockIdx.y * 64;
    int o0 = blockIdx.x * 64;
    int tid = threadIdx.x;
    int tx = tid & 15, ty = tid >> 4;

    __shared__ float xs[16][64];
    __shared__ float ws0[16][64];
    __shared__ float ws1[16][64];
    __shared__ float ws2[16][64];

    float at[4][4] = {}, ap[4][4] = {}, ag[4][4] = {};

    const float* xb = x + (size_t)b * CC * NN;

    for (int kc = 0; kc < CC; kc += 16) {
        // x tile: 16 rows (k) x 64 cols (n)
        {
            int row = tid >> 4;
            int c4  = (tid & 15) * 4;
            *(float4*)&xs[row][c4] = *(const float4*)(xb + (size_t)(kc + row) * NN + n0 + c4);
        }
        // weight tiles: [64 o][16 k] -> transposed into ws[kk][o]
        {
            int o  = tid >> 2;
            int k4 = (tid & 3) * 4;
            float4 v;
            v = *(const float4*)(wt + (size_t)(o0 + o) * CC + kc + k4);
            ws0[k4 + 0][o] = v.x; ws0[k4 + 1][o] = v.y; ws0[k4 + 2][o] = v.z; ws0[k4 + 3][o] = v.w;
            v = *(const float4*)(wp + (size_t)(o0 + o) * CC + kc + k4);
            ws1[k4 + 0][o] = v.x; ws1[k4 + 1][o] = v.y; ws1[k4 + 2][o] = v.z; ws1[k4 + 3][o] = v.w;
            v = *(const float4*)(wg + (size_t)(o0 + o) * CC + kc + k4);
            ws2[k4 + 0][o] = v.x; ws2[k4 + 1][o] = v.y; ws2[k4 + 2][o] = v.z; ws2[k4 + 3][o] = v.w;
        }
        __syncthreads();
        #pragma unroll
        for (int kk = 0; kk < 16; kk++) {
            float bv[4], a0[4], a1[4], a2[4];
            *(float4*)bv = *(float4*)&xs[kk][tx * 4];
            *(float4*)a0 = *(float4*)&ws0[kk][ty * 4];
            *(float4*)a1 = *(float4*)&ws1[kk][ty * 4];
            *(float4*)a2 = *(float4*)&ws2[kk][ty * 4];
            #pragma unroll
            for (int i = 0; i < 4; i++)
                #pragma unroll
                for (int j = 0; j < 4; j++) {
                    at[i][j] += a0[i] * bv[j];
                    ap[i][j] += a1[i] * bv[j];
                    ag[i][j] += a2[i] * bv[j];
                }
        }
        __syncthreads();
    }

    float btv[4], bpv[4], bgv[4];
    #pragma unroll
    for (int i = 0; i < 4; i++) {
        btv[i] = bt[o0 + ty * 4 + i];
        bpv[i] = bp[o0 + ty * 4 + i];
        bgv[i] = bg[o0 + ty * 4 + i];
    }

    float* thb = g_theta + (size_t)b * CI * NN;
    float* phb = g_phi   + (size_t)b * CI * NN;
    float* gbm = g_g     + (size_t)b * NN * CI;

    #pragma unroll
    for (int i = 0; i < 4; i++) {
        int o = o0 + ty * 4 + i;
        float4 v;
        v.x = at[i][0] + btv[i]; v.y = at[i][1] + btv[i];
        v.z = at[i][2] + btv[i]; v.w = at[i][3] + btv[i];
        *(float4*)(thb + (size_t)o * NN + n0 + tx * 4) = v;
        v.x = ap[i][0] + bpv[i]; v.y = ap[i][1] + bpv[i];
        v.z = ap[i][2] + bpv[i]; v.w = ap[i][3] + bpv[i];
        *(float4*)(phb + (size_t)o * NN + n0 + tx * 4) = v;
    }
    // g stored transposed: [n][o]
    #pragma unroll
    for (int j = 0; j < 4; j++) {
        int n = n0 + tx * 4 + j;
        float4 v;
        v.x = ag[0][j] + bgv[0]; v.y = ag[1][j] + bgv[1];
        v.z = ag[2][j] + bgv[2]; v.w = ag[3][j] + bgv[3];
        *(float4*)(gbm + (size_t)n * CI + o0 + ty * 4) = v;
    }
}

// ---------------------------------------------------------------------------
// Kernel 2: flash attention. Per (b, 64-query tile).
// S = theta^T phi (K=256), online softmax, Y += P * G (streamed over 64-key
// tiles). Y kept in registers: thread (tx,ty) owns q rows ty*4+i, o cols
// cc*64 + tx*4+j.
// ---------------------------------------------------------------------------
__global__ __launch_bounds__(256, 2) void attn_kernel()
{
    int b  = blockIdx.y;
    int q0 = blockIdx.x * 64;
    int tid = threadIdx.x;
    int tx = tid & 15, ty = tid >> 4;

    __shared__ float th_s[32][64];
    __shared__ float ph_s[32][64];
    __shared__ float P_s[64][64];
    __shared__ float g_s[64][64];

    float Y[4][16];
    #pragma unroll
    for (int i = 0; i < 4; i++)
        #pragma unroll
        for (int c = 0; c < 16; c++) Y[i][c] = 0.f;

    float m[4], l[4];
    #pragma unroll
    for (int i = 0; i < 4; i++) { m[i] = -1e30f; l[i] = 0.f; }

    const float* thb = g_theta + (size_t)b * CI * NN;
    const float* phb = g_phi   + (size_t)b * CI * NN;
    const float* gbm = g_g     + (size_t)b * NN * CI;

    for (int k0 = 0; k0 < NN; k0 += 64) {
        float s[4][4] = {};
        // --- S = theta^T phi over K=256, chunks of 32 ---
        for (int o0 = 0; o0 < CI; o0 += 32) {
            int r  = tid >> 4;
            int c4 = (tid & 15) * 4;
            *(float4*)&th_s[r][c4]      = *(const float4*)(thb + (size_t)(o0 + r) * NN + q0 + c4);
            *(float4*)&th_s[r + 16][c4] = *(const float4*)(thb + (size_t)(o0 + r + 16) * NN + q0 + c4);
            *(float4*)&ph_s[r][c4]      = *(const float4*)(phb + (size_t)(o0 + r) * NN + k0 + c4);
            *(float4*)&ph_s[r + 16][c4] = *(const float4*)(phb + (size_t)(o0 + r + 16) * NN + k0 + c4);
            __syncthreads();
            #pragma unroll
            for (int oo = 0; oo < 32; oo++) {
                float a[4], bb[4];
                *(float4*)a  = *(float4*)&th_s[oo][ty * 4];
                *(float4*)bb = *(float4*)&ph_s[oo][tx * 4];
                #pragma unroll
                for (int i = 0; i < 4; i++)
                    #pragma unroll
                    for (int j = 0; j < 4; j++) s[i][j] += a[i] * bb[j];
            }
            __syncthreads();
        }
        // --- online softmax update ---
        #pragma unroll
        for (int i = 0; i < 4; i++) {
            float rm = fmaxf(fmaxf(s[i][0], s[i][1]), fmaxf(s[i][2], s[i][3]));
            rm = fmaxf(rm, __shfl_xor_sync(0xffffffffu, rm, 1));
            rm = fmaxf(rm, __shfl_xor_sync(0xffffffffu, rm, 2));
            rm = fmaxf(rm, __shfl_xor_sync(0xffffffffu, rm, 4));
            rm = fmaxf(rm, __shfl_xor_sync(0xffffffffu, rm, 8));
            float mn = fmaxf(m[i], rm);
            float scale = __expf(m[i] - mn);
            float rs = 0.f;
            #pragma unroll
            for (int j = 0; j < 4; j++) { s[i][j] = __expf(s[i][j] - mn); rs += s[i][j]; }
            rs += __shfl_xor_sync(0xffffffffu, rs, 1);
            rs += __shfl_xor_sync(0xffffffffu, rs, 2);
            rs += __shfl_xor_sync(0xffffffffu, rs, 4);
            rs += __shfl_xor_sync(0xffffffffu, rs, 8);
            l[i] = l[i] * scale + rs;
            m[i] = mn;
            #pragma unroll
            for (int c = 0; c < 16; c++) Y[i][c] *= scale;
        }
        // --- stage P to smem ---
        #pragma unroll
        for (int i = 0; i < 4; i++) {
            float4 v; v.x = s[i][0]; v.y = s[i][1]; v.z = s[i][2]; v.w = s[i][3];
            *(float4*)&P_s[ty * 4 + i][tx * 4] = v;
        }
        // --- Y += P * G, o-chunks of 64 ---
        #pragma unroll
        for (int cc = 0; cc < 4; cc++) {
            int r  = tid >> 2;
            int c4 = (tid & 3) * 4;
            #pragma unroll
            for (int p = 0; p < 4; p++)
                *(float4*)&g_s[r][c4 + p * 16] =
                    *(const float4*)(gbm + (size_t)(k0 + r) * CI + cc * 64 + c4 + p * 16);
            __syncthreads();
            #pragma unroll 8
            for (int kk = 0; kk < 64; kk++) {
                float gv[4];
                *(float4*)gv = *(float4*)&g_s[kk][tx * 4];
                #pragma unroll
                for (int i = 0; i < 4; i++) {
                    float pv = P_s[ty * 4 + i][kk];
                    #pragma unroll
                    for (int j = 0; j < 4; j++) Y[i][cc * 4 + j] += pv * gv[j];
                }
            }
            __syncthreads();
        }
    }
    // --- normalize + write y[n][o] ---
    float* yb = g_y + (size_t)b * NN * CI;
    #pragma unroll
    for (int i = 0; i < 4; i++) {
        float inv = 1.f / l[i];
        #pragma unroll
        for (int cc = 0; cc < 4; cc++) {
            float4 v;
            v.x = Y[i][cc * 4 + 0] * inv; v.y = Y[i][cc * 4 + 1] * inv;
            v.z = Y[i][cc * 4 + 2] * inv; v.w = Y[i][cc * 4 + 3] * inv;
            *(float4*)(yb + (size_t)(q0 + ty * 4 + i) * CI + cc * 64 + tx * 4) = v;
        }
    }
}

// ---------------------------------------------------------------------------
// Kernel 3: out[c,n] = sum_o w_out[c,o] * y[n,o] + b_out[c] + x[b,c,n]
// ---------------------------------------------------------------------------
__global__ __launch_bounds__(256) void out_kernel(
    const float* __restrict__ x,
    const float* __restrict__ wo, const float* __restrict__ bo,
    float* __restrict__ out)
{
    int b  = blockIdx.z;
    int n0 = blockIdx.y * 64;
    int c0 = blockIdx.x * 64;
    int tid = threadIdx.x;
    int tx = tid & 15, ty = tid >> 4;

    __shared__ float ws[16][64]; // ws[oo][c]
    __shared__ float ys[16][64]; // ys[oo][n]

    float acc[4][4] = {};
    const float* yb = g_y + (size_t)b * NN * CI;

    for (int oc = 0; oc < CI; oc += 16) {
        {
            int c  = tid >> 2;
            int o4 = (tid & 3) * 4;
            float4 v = *(const float4*)(wo + (size_t)(c0 + c) * CI + oc + o4);
            ws[o4 + 0][c] = v.x; ws[o4 + 1][c] = v.y; ws[o4 + 2][c] = v.z; ws[o4 + 3][c] = v.w;
        }
        {
            int n  = tid >> 2;
            int o4 = (tid & 3) * 4;
            float4 v = *(const float4*)(yb + (size_t)(n0 + n) * CI + oc + o4);
            ys[o4 + 0][n] = v.x; ys[o4 + 1][n] = v.y; ys[o4 + 2][n] = v.z; ys[o4 + 3][n] = v.w;
        }
        __syncthreads();
        #pragma unroll
        for (int kk = 0; kk < 16; kk++) {
            float a[4], bb[4];
            *(float4*)a  = *(float4*)&ws[kk][ty * 4];
            *(float4*)bb = *(float4*)&ys[kk][tx * 4];
            #pragma unroll
            for (int i = 0; i < 4; i++)
                #pragma unroll
                for (int j = 0; j < 4; j++) acc[i][j] += a[i] * bb[j];
        }
        __syncthreads();
    }

    const float* xb = x + (size_t)b * CC * NN;
    float* ob = out + (size_t)b * CC * NN;
    #pragma unroll
    for (int i = 0; i < 4; i++) {
        int c = c0 + ty * 4 + i;
        float bv = bo[c];
        float4 xv = *(const float4*)(xb + (size_t)c * NN + n0 + tx * 4);
        float4 v;
        v.x = acc[i][0] + bv + xv.x; v.y = acc[i][1] + bv + xv.y;
        v.z = acc[i][2] + bv + xv.z; v.w = acc[i][3] + bv + xv.w;
        *(float4*)(ob + (size_t)c * NN + n0 + tx * 4) = v;
    }
}

extern "C" void kernel_launch(void* const* d_in, const int* in_sizes, int n_in,
                              void* d_out, int out_size)
{
    const float* x  = (const float*)d_in[0];
    const float* wt = (const float*)d_in[1];
    const float* bt = (const float*)d_in[2];
    const float* wp = (const float*)d_in[3];
    const float* bp = (const float*)d_in[4];
    const float* wg = (const float*)d_in[5];
    const float* bg = (const float*)d_in[6];
    const float* wo = (const float*)d_in[7];
    const float* bo = (const float*)d_in[8];
    float* out = (float*)d_out;

    dim3 g1(CI / 64, NN / 64, BB);
    proj_kernel<<<g1, 256>>>(x, wt, bt, wp, bp, wg, bg);

    dim3 g2(NN / 64, BB);
    attn_kernel<<<g2, 256>>>();

    dim3 g3(CC / 64, NN / 64, BB);
    out_kernel<<<g3, 256>>>(x, wo, bo, out);
}

// round 2
// speedup vs baseline: 1.0213x; 1.0213x over previous
#include <cuda_runtime.h>
#include <cuda_bf16.h>

#define BB 4
#define CC 512
#define CI 256
#define NN 4096

typedef unsigned long long u64;

// Scratch (device globals; no allocation allowed)
__device__ float g_theta[BB * CI * NN]; // [b][o][n]
__device__ float g_phi[BB * CI * NN];   // [b][o][n]
__device__ float g_g[BB * NN * CI];     // [b][n][o]
__device__ float g_y[BB * NN * CI];     // [b][n][o]

// ---- packed f32x2 helpers (sm_103a packed fp32 pipe; ptxas won't auto-fuse) ----
__device__ __forceinline__ u64 pack_dup(float a) {
    u64 r; asm("mov.b64 %0, {%1, %1};" : "=l"(r) : "f"(a)); return r;
}
__device__ __forceinline__ void ffma2(u64& d, u64 a, u64 b) {
    asm("fma.rn.f32x2 %0, %1, %2, %0;" : "+l"(d) : "l"(a), "l"(b));
}
__device__ __forceinline__ void fmul2ip(u64& d, u64 a) {
    asm("mul.rn.f32x2 %0, %0, %1;" : "+l"(d) : "l"(a));
}
__device__ __forceinline__ float2 unpack2(u64 v) {
    float2 f; asm("mov.b64 {%0, %1}, %2;" : "=f"(f.x), "=f"(f.y) : "l"(v)); return f;
}

// ---------------------------------------------------------------------------
// Kernel 1: fused projections theta/phi/g (f32x2 inner product).
// ---------------------------------------------------------------------------
__global__ __launch_bounds__(256) void proj_kernel(
    const float* __restrict__ x,
    const float* __restrict__ wt, const float* __restrict__ bt,
    const float* __restrict__ wp, const float* __restrict__ bp,
    const float* __restrict__ wg, const float* __restrict__ bg)
{
    int b  = blockIdx.z;
    int n0 = blockIdx.y * 64;
    int o0 = blockIdx.x * 64;
    int tid = threadIdx.x;
    int tx = tid & 15, ty = tid >> 4;

    __shared__ __align__(16) float xs[16][64];
    __shared__ __align__(16) float ws0[16][64];
    __shared__ __align__(16) float ws1[16][64];
    __shared__ __align__(16) float ws2[16][64];

    u64 at2[4][2] = {}, ap2[4][2] = {}, ag2[4][2] = {};

    const float* xb = x + (size_t)b * CC * NN;

    for (int kc = 0; kc < CC; kc += 16) {
        {
            int row = tid >> 4;
            int c4  = (tid & 15) * 4;
            *(float4*)&xs[row][c4] = *(const float4*)(xb + (size_t)(kc + row) * NN + n0 + c4);
        }
        {
            int o  = tid >> 2;
            int k4 = (tid & 3) * 4;
            float4 v;
            v = *(const float4*)(wt + (size_t)(o0 + o) * CC + kc + k4);
            ws0[k4 + 0][o] = v.x; ws0[k4 + 1][o] = v.y; ws0[k4 + 2][o] = v.z; ws0[k4 + 3][o] = v.w;
            v = *(const float4*)(wp + (size_t)(o0 + o) * CC + kc + k4);
            ws1[k4 + 0][o] = v.x; ws1[k4 + 1][o] = v.y; ws1[k4 + 2][o] = v.z; ws1[k4 + 3][o] = v.w;
            v = *(const float4*)(wg + (size_t)(o0 + o) * CC + kc + k4);
            ws2[k4 + 0][o] = v.x; ws2[k4 + 1][o] = v.y; ws2[k4 + 2][o] = v.z; ws2[k4 + 3][o] = v.w;
        }
        __syncthreads();
        #pragma unroll
        for (int kk = 0; kk < 16; kk++) {
            ulonglong2 bp2 = *(const ulonglong2*)&xs[kk][tx * 4];
            float a0[4], a1[4], a2[4];
            *(float4*)a0 = *(float4*)&ws0[kk][ty * 4];
            *(float4*)a1 = *(float4*)&ws1[kk][ty * 4];
            *(float4*)a2 = *(float4*)&ws2[kk][ty * 4];
            #pragma unroll
            for (int i = 0; i < 4; i++) {
                u64 d;
                d = pack_dup(a0[i]); ffma2(at2[i][0], d, bp2.x); ffma2(at2[i][1], d, bp2.y);
                d = pack_dup(a1[i]); ffma2(ap2[i][0], d, bp2.x); ffma2(ap2[i][1], d, bp2.y);
                d = pack_dup(a2[i]); ffma2(ag2[i][0], d, bp2.x); ffma2(ag2[i][1], d, bp2.y);
            }
        }
        __syncthreads();
    }

    float btv[4], bpv[4], bgv[4];
    #pragma unroll
    for (int i = 0; i < 4; i++) {
        btv[i] = bt[o0 + ty * 4 + i];
        bpv[i] = bp[o0 + ty * 4 + i];
        bgv[i] = bg[o0 + ty * 4 + i];
    }

    float* thb = g_theta + (size_t)b * CI * NN;
    float* phb = g_phi   + (size_t)b * CI * NN;
    float* gbm = g_g     + (size_t)b * NN * CI;

    #pragma unroll
    for (int i = 0; i < 4; i++) {
        int o = o0 + ty * 4 + i;
        float2 p0 = unpack2(at2[i][0]), p1 = unpack2(at2[i][1]);
        float4 v;
        v.x = p0.x + btv[i]; v.y = p0.y + btv[i]; v.z = p1.x + btv[i]; v.w = p1.y + btv[i];
        *(float4*)(thb + (size_t)o * NN + n0 + tx * 4) = v;
        p0 = unpack2(ap2[i][0]); p1 = unpack2(ap2[i][1]);
        v.x = p0.x + bpv[i]; v.y = p0.y + bpv[i]; v.z = p1.x + bpv[i]; v.w = p1.y + bpv[i];
        *(float4*)(phb + (size_t)o * NN + n0 + tx * 4) = v;
    }
    // g stored transposed: [n][o]
    float ag[4][4];
    #pragma unroll
    for (int i = 0; i < 4; i++) {
        float2 p0 = unpack2(ag2[i][0]), p1 = unpack2(ag2[i][1]);
        ag[i][0] = p0.x; ag[i][1] = p0.y; ag[i][2] = p1.x; ag[i][3] = p1.y;
    }
    #pragma unroll
    for (int j = 0; j < 4; j++) {
        int n = n0 + tx * 4 + j;
        float4 v;
        v.x = ag[0][j] + bgv[0]; v.y = ag[1][j] + bgv[1];
        v.z = ag[2][j] + bgv[2]; v.w = ag[3][j] + bgv[3];
        *(float4*)(gbm + (size_t)n * CI + o0 + ty * 4) = v;
    }
}

// ---------------------------------------------------------------------------
// Kernel 2: flash attention with f32x2 GEMM cores.
// ---------------------------------------------------------------------------
__global__ __launch_bounds__(256, 2) void attn_kernel()
{
    int b  = blockIdx.y;
    int q0 = blockIdx.x * 64;
    int tid = threadIdx.x;
    int tx = tid & 15, ty = tid >> 4;

    __shared__ __align__(16) float th_s[32][64];
    __shared__ __align__(16) float ph_s[32][64];
    __shared__ __align__(16) float P_s[64][64];
    __shared__ __align__(16) float g_s[64][64];

    u64 Y2[4][8] = {};  // [row i][8 pairs = 16 o-cols]

    float m[4], l[4];
    #pragma unroll
    for (int i = 0; i < 4; i++) { m[i] = -1e30f; l[i] = 0.f; }

    const float* thb = g_theta + (size_t)b * CI * NN;
    const float* phb = g_phi   + (size_t)b * CI * NN;
    const float* gbm = g_g     + (size_t)b * NN * CI;

    for (int k0 = 0; k0 < NN; k0 += 64) {
        u64 s2[4][2] = {};
        // --- S = theta^T phi over K=256, chunks of 32 ---
        for (int o0 = 0; o0 < CI; o0 += 32) {
            int r  = tid >> 4;
            int c4 = (tid & 15) * 4;
            *(float4*)&th_s[r][c4]      = *(const float4*)(thb + (size_t)(o0 + r) * NN + q0 + c4);
            *(float4*)&th_s[r + 16][c4] = *(const float4*)(thb + (size_t)(o0 + r + 16) * NN + q0 + c4);
            *(float4*)&ph_s[r][c4]      = *(const float4*)(phb + (size_t)(o0 + r) * NN + k0 + c4);
            *(float4*)&ph_s[r + 16][c4] = *(const float4*)(phb + (size_t)(o0 + r + 16) * NN + k0 + c4);
            __syncthreads();
            #pragma unroll
            for (int oo = 0; oo < 32; oo++) {
                ulonglong2 bp2 = *(const ulonglong2*)&ph_s[oo][tx * 4];
                float a[4];
                *(float4*)a = *(float4*)&th_s[oo][ty * 4];
                #pragma unroll
                for (int i = 0; i < 4; i++) {
                    u64 d = pack_dup(a[i]);
                    ffma2(s2[i][0], d, bp2.x);
                    ffma2(s2[i][1], d, bp2.y);
                }
            }
            __syncthreads();
        }
        // --- online softmax update ---
        float s[4][4];
        #pragma unroll
        for (int i = 0; i < 4; i++) {
            float2 p0 = unpack2(s2[i][0]), p1 = unpack2(s2[i][1]);
            s[i][0] = p0.x; s[i][1] = p0.y; s[i][2] = p1.x; s[i][3] = p1.y;
        }
        #pragma unroll
        for (int i = 0; i < 4; i++) {
            float rm = fmaxf(fmaxf(s[i][0], s[i][1]), fmaxf(s[i][2], s[i][3]));
            rm = fmaxf(rm, __shfl_xor_sync(0xffffffffu, rm, 1));
            rm = fmaxf(rm, __shfl_xor_sync(0xffffffffu, rm, 2));
            rm = fmaxf(rm, __shfl_xor_sync(0xffffffffu, rm, 4));
            rm = fmaxf(rm, __shfl_xor_sync(0xffffffffu, rm, 8));
            float mn = fmaxf(m[i], rm);
            float scale = __expf(m[i] - mn);
            float rs = 0.f;
            #pragma unroll
            for (int j = 0; j < 4; j++) { s[i][j] = __expf(s[i][j] - mn); rs += s[i][j]; }
            rs += __shfl_xor_sync(0xffffffffu, rs, 1);
            rs += __shfl_xor_sync(0xffffffffu, rs, 2);
            rs += __shfl_xor_sync(0xffffffffu, rs, 4);
            rs += __shfl_xor_sync(0xffffffffu, rs, 8);
            l[i] = l[i] * scale + rs;
            m[i] = mn;
            u64 sc = pack_dup(scale);
            #pragma unroll
            for (int c = 0; c < 8; c++) fmul2ip(Y2[i][c], sc);
        }
        // --- stage P to smem ---
        #pragma unroll
        for (int i = 0; i < 4; i++) {
            float4 v; v.x = s[i][0]; v.y = s[i][1]; v.z = s[i][2]; v.w = s[i][3];
            *(float4*)&P_s[ty * 4 + i][tx * 4] = v;
        }
        // --- Y += P * G, o-chunks of 64 ---
        #pragma unroll
        for (int cc = 0; cc < 4; cc++) {
            int r  = tid >> 2;
            int c4 = (tid & 3) * 4;
            #pragma unroll
            for (int p = 0; p < 4; p++)
                *(float4*)&g_s[r][c4 + p * 16] =
                    *(const float4*)(gbm + (size_t)(k0 + r) * CI + cc * 64 + c4 + p * 16);
            __syncthreads();
            #pragma unroll 8
            for (int kk = 0; kk < 64; kk++) {
                ulonglong2 gp2 = *(const ulonglong2*)&g_s[kk][tx * 4];
                #pragma unroll
                for (int i = 0; i < 4; i++) {
                    u64 pd = pack_dup(P_s[ty * 4 + i][kk]);
                    ffma2(Y2[i][cc * 2 + 0], pd, gp2.x);
                    ffma2(Y2[i][cc * 2 + 1], pd, gp2.y);
                }
            }
            __syncthreads();
        }
    }
    // --- normalize + write y[n][o] ---
    float* yb = g_y + (size_t)b * NN * CI;
    #pragma unroll
    for (int i = 0; i < 4; i++) {
        float inv = 1.f / l[i];
        #pragma unroll
        for (int cc = 0; cc < 4; cc++) {
            float2 p0 = unpack2(Y2[i][cc * 2 + 0]);
            float2 p1 = unpack2(Y2[i][cc * 2 + 1]);
            float4 v;
            v.x = p0.x * inv; v.y = p0.y * inv; v.z = p1.x * inv; v.w = p1.y * inv;
            *(float4*)(yb + (size_t)(q0 + ty * 4 + i) * CI + cc * 64 + tx * 4) = v;
        }
    }
}

// ---------------------------------------------------------------------------
// Kernel 3: out[c,n] = sum_o w_out[c,o] * y[n,o] + b_out[c] + x[b,c,n]
// ---------------------------------------------------------------------------
__global__ __launch_bounds__(256) void out_kernel(
    const float* __restrict__ x,
    const float* __restrict__ wo, const float* __restrict__ bo,
    float* __restrict__ out)
{
    int b  = blockIdx.z;
    int n0 = blockIdx.y * 64;
    int c0 = blockIdx.x * 64;
    int tid = threadIdx.x;
    int tx = tid & 15, ty = tid >> 4;

    __shared__ __align__(16) float ws[16][64]; // ws[oo][c]
    __shared__ __align__(16) float ys[16][64]; // ys[oo][n]

    u64 acc2[4][2] = {};
    const float* yb = g_y + (size_t)b * NN * CI;

    for (int oc = 0; oc < CI; oc += 16) {
        {
            int c  = tid >> 2;
            int o4 = (tid & 3) * 4;
            float4 v = *(const float4*)(wo + (size_t)(c0 + c) * CI + oc + o4);
            ws[o4 + 0][c] = v.x; ws[o4 + 1][c] = v.y; ws[o4 + 2][c] = v.z; ws[o4 + 3][c] = v.w;
        }
        {
            int n  = tid >> 2;
            int o4 = (tid & 3) * 4;
            float4 v = *(const float4*)(yb + (size_t)(n0 + n) * CI + oc + o4);
            ys[o4 + 0][n] = v.x; ys[o4 + 1][n] = v.y; ys[o4 + 2][n] = v.z; ys[o4 + 3][n] = v.w;
        }
        __syncthreads();
        #pragma unroll
        for (int kk = 0; kk < 16; kk++) {
            ulonglong2 bp2 = *(const ulonglong2*)&ys[kk][tx * 4];
            float a[4];
            *(float4*)a = *(float4*)&ws[kk][ty * 4];
            #pragma unroll
            for (int i = 0; i < 4; i++) {
                u64 d = pack_dup(a[i]);
                ffma2(acc2[i][0], d, bp2.x);
                ffma2(acc2[i][1], d, bp2.y);
            }
        }
        __syncthreads();
    }

    const float* xb = x + (size_t)b * CC * NN;
    float* ob = out + (size_t)b * CC * NN;
    #pragma unroll
    for (int i = 0; i < 4; i++) {
        int c = c0 + ty * 4 + i;
        float bv = bo[c];
        float4 xv = *(const float4*)(xb + (size_t)c * NN + n0 + tx * 4);
        float2 p0 = unpack2(acc2[i][0]), p1 = unpack2(acc2[i][1]);
        float4 v;
        v.x = p0.x + bv + xv.x; v.y = p0.y + bv + xv.y;
        v.z = p1.x + bv + xv.z; v.w = p1.y + bv + xv.w;
        *(float4*)(ob + (size_t)c * NN + n0 + tx * 4) = v;
    }
}

extern "C" void kernel_launch(void* const* d_in, const int* in_sizes, int n_in,
                              void* d_out, int out_size)
{
    const float* x  = (const float*)d_in[0];
    const float* wt = (const float*)d_in[1];
    const float* bt = (const float*)d_in[2];
    const float* wp = (const float*)d_in[3];
    const float* bp = (const float*)d_in[4];
    const float* wg = (const float*)d_in[5];
    const float* bg = (const float*)d_in[6];
    const float* wo = (const float*)d_in[7];
    const float* bo = (const float*)d_in[8];
    float* out = (float*)d_out;

    dim3 g1(CI / 64, NN / 64, BB);
    proj_kernel<<<g1, 256>>>(x, wt, bt, wp, bp, wg, bg);

    dim3 g2(NN / 64, BB);
    attn_kernel<<<g2, 256>>>();

    dim3 g3(CC / 64, NN / 64, BB);
    out_kernel<<<g3, 256>>>(x, wo, bo, out);
}

// round 11
// speedup vs baseline: 2.6730x; 2.6171x over previous
#include <cuda_runtime.h>
#include <cuda_bf16.h>
#include <cuda_fp16.h>
#include <cstdint>

#define BB 4
#define CC 512
#define CI 256
#define NN 4096
#define QT 128

typedef unsigned long long u64;
typedef unsigned int u32;

// ---------------- device scratch (no allocation allowed) ----------------
__device__ __align__(256) __nv_bfloat16 g_th_hi[BB * NN * CI]; // theta [b][n][o]
__device__ __align__(256) __nv_bfloat16 g_th_lo[BB * NN * CI];
__device__ __align__(256) __nv_bfloat16 g_ph_hi[BB * NN * CI]; // phi   [b][n][o]
__device__ __align__(256) __nv_bfloat16 g_ph_lo[BB * NN * CI];
__device__ __align__(256) __half       g_g16 [BB * CI * NN];   // g     [b][o][n] fp16
__device__ __align__(256) float        g_y   [BB * NN * CI];   // y     [b][n][o]

// ---------------- PTX helpers ----------------
__device__ __forceinline__ void cp16(u32 dst, const void* src) {
    asm volatile("cp.async.ca.shared.global [%0], [%1], 16;" :: "r"(dst), "l"(src));
}
#define CP_COMMIT() asm volatile("cp.async.commit_group;" ::: "memory")
#define CP_WAIT0()  asm volatile("cp.async.wait_group 0;" ::: "memory")

__device__ __forceinline__ u32 smem_u32(const void* p) {
    u32 a;
    asm("{ .reg .u64 t; cvta.to.shared.u64 t, %1; cvt.u32.u64 %0, t; }" : "=r"(a) : "l"(p));
    return a;
}
__device__ __forceinline__ void mma_bf16(float c[4], const u32 a[4], const u32 b[2]) {
    asm volatile("mma.sync.aligned.m16n8k16.row.col.f32.bf16.bf16.f32 "
                 "{%0,%1,%2,%3}, {%4,%5,%6,%7}, {%8,%9}, {%0,%1,%2,%3};"
                 : "+f"(c[0]), "+f"(c[1]), "+f"(c[2]), "+f"(c[3])
                 : "r"(a[0]), "r"(a[1]), "r"(a[2]), "r"(a[3]), "r"(b[0]), "r"(b[1]));
}
__device__ __forceinline__ void mma_f16(float c[4], const u32 a[4], const u32 b[2]) {
    asm volatile("mma.sync.aligned.m16n8k16.row.col.f32.f16.f16.f32 "
                 "{%0,%1,%2,%3}, {%4,%5,%6,%7}, {%8,%9}, {%0,%1,%2,%3};"
                 : "+f"(c[0]), "+f"(c[1]), "+f"(c[2]), "+f"(c[3])
                 : "r"(a[0]), "r"(a[1]), "r"(a[2]), "r"(a[3]), "r"(b[0]), "r"(b[1]));
}
__device__ __forceinline__ u32 pack_bf2(float a, float b) {
    u32 ra = (u32)__bfloat16_as_ushort(__float2bfloat16_rn(a));
    u32 rb = (u32)__bfloat16_as_ushort(__float2bfloat16_rn(b));
    return ra | (rb << 16);
}
__device__ __forceinline__ float bf_hi(float v) {
    return __bfloat162float(__float2bfloat16_rn(v));
}
__device__ __forceinline__ u32 pack_h2(float a, float b) {
    __half2 h = __floats2half2_rn(a, b);
    return *(u32*)&h;
}

// ---- smem layout (byte offsets). Row pitches chosen ≡ 4 mod 32 words ----
// theta hi/lo: [128 q][256 o] bf16, pitch 264 b16 = 528 B
#define TH_HI_OFF 0
#define TH_LO_OFF 67584
// phi chunk: 2 bufs x { hi [64 n][64 o] pitch 72 b16 = 144 B ; lo same }
#define PH_OFF    135168
#define PH_BUF    18432
#define PH_LO     9216
// P: [128 q][64 k] fp16, pitch 72 -> 144 B
#define P_OFF     172032
// G: [256 o][64 k] fp16, pitch 72 -> 144 B
#define G_OFF     190464
#define DYN_SMEM  227328

// ---------------------------------------------------------------------------
// Kernel 1: projections -> theta/phi bf16 hi+lo [b][n][o], g fp16 [b][o][n]
// ---------------------------------------------------------------------------
__global__ __launch_bounds__(256) void proj_kernel(
    const float* __restrict__ x,
    const float* __restrict__ wt, const float* __restrict__ bt,
    const float* __restrict__ wp, const float* __restrict__ bp,
    const float* __restrict__ wg, const float* __restrict__ bg)
{
    int b  = blockIdx.z;
    int n0 = blockIdx.y * 64;
    int o0 = blockIdx.x * 64;
    int tid = threadIdx.x;
    int tx = tid & 15, ty = tid >> 4;

    __shared__ float xs[16][64];
    __shared__ float ws0[16][64];
    __shared__ float ws1[16][64];
    __shared__ float ws2[16][64];

    float at[4][4] = {}, ap[4][4] = {}, ag[4][4] = {};
    const float* xb = x + (size_t)b * CC * NN;

    for (int kc = 0; kc < CC; kc += 16) {
        {
            int row = tid >> 4;
            int c4  = (tid & 15) * 4;
            *(float4*)&xs[row][c4] = *(const float4*)(xb + (size_t)(kc + row) * NN + n0 + c4);
        }
        {
            int o  = tid >> 2;
            int k4 = (tid & 3) * 4;
            float4 v;
            v = *(const float4*)(wt + (size_t)(o0 + o) * CC + kc + k4);
            ws0[k4+0][o] = v.x; ws0[k4+1][o] = v.y; ws0[k4+2][o] = v.z; ws0[k4+3][o] = v.w;
            v = *(const float4*)(wp + (size_t)(o0 + o) * CC + kc + k4);
            ws1[k4+0][o] = v.x; ws1[k4+1][o] = v.y; ws1[k4+2][o] = v.z; ws1[k4+3][o] = v.w;
            v = *(const float4*)(wg + (size_t)(o0 + o) * CC + kc + k4);
            ws2[k4+0][o] = v.x; ws2[k4+1][o] = v.y; ws2[k4+2][o] = v.z; ws2[k4+3][o] = v.w;
        }
        __syncthreads();
        #pragma unroll
        for (int kk = 0; kk < 16; kk++) {
            float bv[4], a0[4], a1[4], a2[4];
            *(float4*)bv = *(float4*)&xs[kk][tx * 4];
            *(float4*)a0 = *(float4*)&ws0[kk][ty * 4];
            *(float4*)a1 = *(float4*)&ws1[kk][ty * 4];
            *(float4*)a2 = *(float4*)&ws2[kk][ty * 4];
            #pragma unroll
            for (int i = 0; i < 4; i++)
                #pragma unroll
                for (int j = 0; j < 4; j++) {
                    at[i][j] += a0[i] * bv[j];
                    ap[i][j] += a1[i] * bv[j];
                    ag[i][j] += a2[i] * bv[j];
                }
        }
        __syncthreads();
    }

    float btv[4], bpv[4], bgv[4];
    #pragma unroll
    for (int i = 0; i < 4; i++) {
        btv[i] = bt[o0 + ty * 4 + i];
        bpv[i] = bp[o0 + ty * 4 + i];
        bgv[i] = bg[o0 + ty * 4 + i];
    }

    size_t bno = (size_t)b * NN * CI;
    size_t bon = (size_t)b * CI * NN;

    // theta/phi: [n][o] hi/lo splits
    #pragma unroll
    for (int j = 0; j < 4; j++) {
        int n = n0 + tx * 4 + j;
        size_t base = bno + (size_t)n * CI + o0 + ty * 4;

        float v0 = at[0][j] + btv[0], v1 = at[1][j] + btv[1];
        float v2 = at[2][j] + btv[2], v3 = at[3][j] + btv[3];
        float h0 = bf_hi(v0), h1 = bf_hi(v1), h2 = bf_hi(v2), h3 = bf_hi(v3);
        uint2 hh, ll;
        hh.x = pack_bf2(h0, h1); hh.y = pack_bf2(h2, h3);
        ll.x = pack_bf2(v0 - h0, v1 - h1); ll.y = pack_bf2(v2 - h2, v3 - h3);
        *(uint2*)(g_th_hi + base) = hh;
        *(uint2*)(g_th_lo + base) = ll;

        v0 = ap[0][j] + bpv[0]; v1 = ap[1][j] + bpv[1];
        v2 = ap[2][j] + bpv[2]; v3 = ap[3][j] + bpv[3];
        h0 = bf_hi(v0); h1 = bf_hi(v1); h2 = bf_hi(v2); h3 = bf_hi(v3);
        hh.x = pack_bf2(h0, h1); hh.y = pack_bf2(h2, h3);
        ll.x = pack_bf2(v0 - h0, v1 - h1); ll.y = pack_bf2(v2 - h2, v3 - h3);
        *(uint2*)(g_ph_hi + base) = hh;
        *(uint2*)(g_ph_lo + base) = ll;
    }
    // g: [o][n] fp16
    #pragma unroll
    for (int i = 0; i < 4; i++) {
        int o = o0 + ty * 4 + i;
        float v0 = ag[i][0] + bgv[i], v1 = ag[i][1] + bgv[i];
        float v2 = ag[i][2] + bgv[i], v3 = ag[i][3] + bgv[i];
        uint2 gg;
        gg.x = pack_h2(v0, v1); gg.y = pack_h2(v2, v3);
        *(uint2*)(g_g16 + bon + (size_t)o * NN + n0 + tx * 4) = gg;
    }
}

// ---------------------------------------------------------------------------
// Kernel 2: mma.sync flash attention. Canonical fragment indexing, no swizzle.
// Warp w owns q rows [w*16, w*16+16). 64-key tiles.
// ---------------------------------------------------------------------------
__global__ __launch_bounds__(256, 1) void attn_kernel()
{
    extern __shared__ __align__(1024) char dsm[];
    u32 dyn = smem_u32(dsm);

    int b    = blockIdx.y;
    int q0   = blockIdx.x * QT;
    int tid  = threadIdx.x;
    int lane = tid & 31;
    int wid  = tid >> 5;
    int q0w  = wid * 16;
    int gid  = lane >> 2;     // 0..7
    int tig  = lane & 3;      // 0..3

    const __nv_bfloat16* th_hi = g_th_hi + (size_t)b * NN * CI;
    const __nv_bfloat16* th_lo = g_th_lo + (size_t)b * NN * CI;
    const __nv_bfloat16* ph_hi = g_ph_hi + (size_t)b * NN * CI;
    const __nv_bfloat16* ph_lo = g_ph_lo + (size_t)b * NN * CI;
    const __half*        gg    = g_g16  + (size_t)b * CI * NN;

    // ---- prologue: theta hi/lo resident in smem ----
    for (int idx = tid; idx < 4096; idx += 256) {
        int r = idx >> 5, c = idx & 31;   // row, 16B chunk
        *(uint4*)(dsm + TH_HI_OFF + r * 528 + c * 16) =
            *(const uint4*)(th_hi + (size_t)(q0 + r) * CI + c * 8);
        *(uint4*)(dsm + TH_LO_OFF + r * 528 + c * 16) =
            *(const uint4*)(th_lo + (size_t)(q0 + r) * CI + c * 8);
    }

    auto issue_phi = [&](int t_, int oc_, int buf) {
        #pragma unroll
        for (int i = 0; i < 2; i++) {
            int idx = tid + i * 256;
            int r = idx >> 3, c = idx & 7;     // r: key row 0..63, c: 16B chunk
            u32 d = dyn + PH_OFF + buf * PH_BUF + r * 144 + c * 16;
            cp16(d, ph_hi + (size_t)(t_ * 64 + r) * CI + oc_ * 64 + c * 8);
            cp16(d + PH_LO, ph_lo + (size_t)(t_ * 64 + r) * CI + oc_ * 64 + c * 8);
        }
    };
    auto issue_g = [&](int t_) {
        #pragma unroll
        for (int i = 0; i < 8; i++) {
            int idx = tid + i * 256;
            int r = idx >> 3, c = idx & 7;     // r: o row 0..255, c: 16B chunk
            cp16(dyn + G_OFF + r * 144 + c * 16,
                 gg + (size_t)r * NN + t_ * 64 + c * 8);
        }
    };

    issue_phi(0, 0, 0);
    CP_COMMIT();

    float M0 = -1e30f, M1 = -1e30f, l0 = 0.f, l1 = 0.f;
    float yacc[32][4];
    #pragma unroll
    for (int k = 0; k < 32; k++)
        #pragma unroll
        for (int j = 0; j < 4; j++) yacc[k][j] = 0.f;

    for (int t = 0; t < 64; t++) {
        float sf[8][4];
        #pragma unroll
        for (int nb = 0; nb < 8; nb++)
            #pragma unroll
            for (int j = 0; j < 4; j++) sf[nb][j] = 0.f;

        // ===== S = theta . phi^T over 4 o-chunks of 64 =====
        for (int oc = 0; oc < 4; oc++) {
            CP_WAIT0();
            __syncthreads();
            // prefetch next
            if (oc < 3) issue_phi(t, oc + 1, (oc + 1) & 1);
            else { issue_g(t); if (t < 63) issue_phi(t + 1, 0, 0); }
            CP_COMMIT();

            u32 phb = dyn + PH_OFF + (oc & 1) * PH_BUF;
            #pragma unroll
            for (int ks = 0; ks < 4; ks++) {
                // A fragments: theta rows q0w+gid(+8), cols oc*64+ks*16+2tig(+8)
                u32 acol = (oc * 64 + ks * 16 + 2 * tig) * 2;
                u32 a0 = TH_HI_OFF + (q0w + gid) * 528 + acol;
                u32 ah[4], al[4];
                ah[0] = *(const u32*)(dsm + a0);
                ah[1] = *(const u32*)(dsm + a0 + 8 * 528);
                ah[2] = *(const u32*)(dsm + a0 + 16);
                ah[3] = *(const u32*)(dsm + a0 + 8 * 528 + 16);
                al[0] = *(const u32*)(dsm + a0 + (TH_LO_OFF - TH_HI_OFF));
                al[1] = *(const u32*)(dsm + a0 + (TH_LO_OFF - TH_HI_OFF) + 8 * 528);
                al[2] = *(const u32*)(dsm + a0 + (TH_LO_OFF - TH_HI_OFF) + 16);
                al[3] = *(const u32*)(dsm + a0 + (TH_LO_OFF - TH_HI_OFF) + 8 * 528 + 16);
                #pragma unroll
                for (int nb = 0; nb < 8; nb++) {
                    // B fragments: phi rows nb*8+gid, cols ks*16+2tig(+8)
                    u32 boff = (phb - dyn) + (nb * 8 + gid) * 144 + (ks * 16 + 2 * tig) * 2;
                    u32 bh[2], bl[2];
                    bh[0] = *(const u32*)(dsm + boff);
                    bh[1] = *(const u32*)(dsm + boff + 16);
                    bl[0] = *(const u32*)(dsm + boff + PH_LO);
                    bl[1] = *(const u32*)(dsm + boff + PH_LO + 16);
                    mma_bf16(sf[nb], ah, bh);
                    mma_bf16(sf[nb], ah, bl);
                    mma_bf16(sf[nb], al, bh);
                }
            }
        }

        // ===== online softmax =====
        float mx0 = -1e30f, mx1 = -1e30f;
        #pragma unroll
        for (int nb = 0; nb < 8; nb++) {
            mx0 = fmaxf(mx0, fmaxf(sf[nb][0], sf[nb][1]));
            mx1 = fmaxf(mx1, fmaxf(sf[nb][2], sf[nb][3]));
        }
        mx0 = fmaxf(mx0, __shfl_xor_sync(0xffffffffu, mx0, 1));
        mx0 = fmaxf(mx0, __shfl_xor_sync(0xffffffffu, mx0, 2));
        mx1 = fmaxf(mx1, __shfl_xor_sync(0xffffffffu, mx1, 1));
        mx1 = fmaxf(mx1, __shfl_xor_sync(0xffffffffu, mx1, 2));

        float Mn0 = fmaxf(M0, mx0), Mn1 = fmaxf(M1, mx1);
        if (Mn0 > M0 || Mn1 > M1) {
            float sc0 = __expf(M0 - Mn0), sc1 = __expf(M1 - Mn1);
            M0 = Mn0; M1 = Mn1;
            l0 *= sc0; l1 *= sc1;
            #pragma unroll
            for (int k = 0; k < 32; k++) {
                yacc[k][0] *= sc0; yacc[k][1] *= sc0;
                yacc[k][2] *= sc1; yacc[k][3] *= sc1;
            }
        }

        // exp + store P (fp16), rows q0w+gid and q0w+gid+8
        u32 p0off = P_OFF + (q0w + gid) * 144 + 2 * tig * 2;
        #pragma unroll
        for (int nb = 0; nb < 8; nb++) {
            float p0 = __expf(sf[nb][0] - M0);
            float p1 = __expf(sf[nb][1] - M0);
            float p2 = __expf(sf[nb][2] - M1);
            float p3 = __expf(sf[nb][3] - M1);
            l0 += p0 + p1;
            l1 += p2 + p3;
            *(u32*)(dsm + p0off + nb * 16)           = pack_h2(p0, p1);
            *(u32*)(dsm + p0off + nb * 16 + 8 * 144) = pack_h2(p2, p3);
        }

        // G tile (and next phi) must be resident before PV
        CP_WAIT0();
        __syncthreads();

        // ===== Y += P . G =====
        #pragma unroll
        for (int ks = 0; ks < 4; ks++) {
            u32 pa = P_OFF + (q0w + gid) * 144 + (ks * 16 + 2 * tig) * 2;
            u32 ap[4];
            ap[0] = *(const u32*)(dsm + pa);
            ap[1] = *(const u32*)(dsm + pa + 8 * 144);
            ap[2] = *(const u32*)(dsm + pa + 16);
            ap[3] = *(const u32*)(dsm + pa + 8 * 144 + 16);
            #pragma unroll
            for (int nt = 0; nt < 32; nt++) {
                u32 gb = G_OFF + (nt * 8 + gid) * 144 + (ks * 16 + 2 * tig) * 2;
                u32 bg[2];
                bg[0] = *(const u32*)(dsm + gb);
                bg[1] = *(const u32*)(dsm + gb + 16);
                mma_f16(yacc[nt], ap, bg);
            }
        }
        __syncthreads();   // all warps done with G before next tile's loads land
    }

    // ===== epilogue =====
    l0 += __shfl_xor_sync(0xffffffffu, l0, 1);
    l0 += __shfl_xor_sync(0xffffffffu, l0, 2);
    l1 += __shfl_xor_sync(0xffffffffu, l1, 1);
    l1 += __shfl_xor_sync(0xffffffffu, l1, 2);
    float inv0 = 1.f / l0, inv1 = 1.f / l1;

    int r0 = q0 + q0w + gid;
    float* yb = g_y + (size_t)b * NN * CI;
    #pragma unroll
    for (int nt = 0; nt < 32; nt++) {
        int o = nt * 8 + 2 * tig;
        float2 v0 = { yacc[nt][0] * inv0, yacc[nt][1] * inv0 };
        float2 v1 = { yacc[nt][2] * inv1, yacc[nt][3] * inv1 };
        *(float2*)(yb + (size_t)r0 * CI + o)       = v0;
        *(float2*)(yb + (size_t)(r0 + 8) * CI + o) = v1;
    }
}

// ---------------------------------------------------------------------------
// Kernel 3: out[c,n] = sum_o w_out[c,o]*y[n,o] + b_out[c] + x[b,c,n]
// ---------------------------------------------------------------------------
__global__ __launch_bounds__(256) void out_kernel(
    const float* __restrict__ x,
    const float* __restrict__ wo, const float* __restrict__ bo,
    float* __restrict__ out)
{
    int b  = blockIdx.z;
    int n0 = blockIdx.y * 64;
    int c0 = blockIdx.x * 64;
    int tid = threadIdx.x;
    int tx = tid & 15, ty = tid >> 4;

    __shared__ float ws[16][64];
    __shared__ float ys[16][64];

    float acc[4][4] = {};
    const float* yb = g_y + (size_t)b * NN * CI;

    for (int oc = 0; oc < CI; oc += 16) {
        {
            int c  = tid >> 2;
            int o4 = (tid & 3) * 4;
            float4 v = *(const float4*)(wo + (size_t)(c0 + c) * CI + oc + o4);
            ws[o4+0][c] = v.x; ws[o4+1][c] = v.y; ws[o4+2][c] = v.z; ws[o4+3][c] = v.w;
        }
        {
            int n  = tid >> 2;
            int o4 = (tid & 3) * 4;
            float4 v = *(const float4*)(yb + (size_t)(n0 + n) * CI + oc + o4);
            ys[o4+0][n] = v.x; ys[o4+1][n] = v.y; ys[o4+2][n] = v.z; ys[o4+3][n] = v.w;
        }
        __syncthreads();
        #pragma unroll
        for (int kk = 0; kk < 16; kk++) {
            float a[4], bb[4];
            *(float4*)a  = *(float4*)&ws[kk][ty * 4];
            *(float4*)bb = *(float4*)&ys[kk][tx * 4];
            #pragma unroll
            for (int i = 0; i < 4; i++)
                #pragma unroll
                for (int j = 0; j < 4; j++) acc[i][j] += a[i] * bb[j];
        }
        __syncthreads();
    }

    const float* xb = x + (size_t)b * CC * NN;
    float* ob = out + (size_t)b * CC * NN;
    #pragma unroll
    for (int i = 0; i < 4; i++) {
        int c = c0 + ty * 4 + i;
        float bv = bo[c];
        float4 xv = *(const float4*)(xb + (size_t)c * NN + n0 + tx * 4);
        float4 v;
        v.x = acc[i][0] + bv + xv.x; v.y = acc[i][1] + bv + xv.y;
        v.z = acc[i][2] + bv + xv.z; v.w = acc[i][3] + bv + xv.w;
        *(float4*)(ob + (size_t)c * NN + n0 + tx * 4) = v;
    }
}

extern "C" void kernel_launch(void* const* d_in, const int* in_sizes, int n_in,
                              void* d_out, int out_size)
{
    const float* x  = (const float*)d_in[0];
    const float* wt = (const float*)d_in[1];
    const float* bt = (const float*)d_in[2];
    const float* wp = (const float*)d_in[3];
    const float* bp = (const float*)d_in[4];
    const float* wg = (const float*)d_in[5];
    const float* bg = (const float*)d_in[6];
    const float* wo = (const float*)d_in[7];
    const float* bo = (const float*)d_in[8];
    float* out = (float*)d_out;

    cudaFuncSetAttribute(attn_kernel, cudaFuncAttributeMaxDynamicSharedMemorySize, DYN_SMEM);

    dim3 g1(CI / 64, NN / 64, BB);
    proj_kernel<<<g1, 256>>>(x, wt, bt, wp, bp, wg, bg);

    dim3 g2(NN / QT, BB);
    attn_kernel<<<g2, 256, DYN_SMEM>>>();

    dim3 g3(CC / 64, NN / 64, BB);
    out_kernel<<<g3, 256>>>(x, wo, bo, out);
}

// round 15
// speedup vs baseline: 3.7404x; 1.3993x over previous
#include <cuda_runtime.h>
#include <cuda_bf16.h>
#include <cuda_fp16.h>
#include <cstdint>

#define BB 4
#define CC 512
#define CI 256
#define NN 4096
#define QT 128

typedef unsigned long long u64;
typedef unsigned int u32;

// ---------------- device scratch (no allocation allowed) ----------------
__device__ __align__(256) __nv_bfloat16 g_xt_hi[BB * NN * CC]; // x^T [b][n][c]
__device__ __align__(256) __nv_bfloat16 g_xt_lo[BB * NN * CC];
__device__ __align__(256) __nv_bfloat16 g_wt_hi[CI * CC];
__device__ __align__(256) __nv_bfloat16 g_wt_lo[CI * CC];
__device__ __align__(256) __nv_bfloat16 g_wp_hi[CI * CC];
__device__ __align__(256) __nv_bfloat16 g_wp_lo[CI * CC];
__device__ __align__(256) __nv_bfloat16 g_wg_hi[CI * CC];
__device__ __align__(256) __nv_bfloat16 g_wg_lo[CI * CC];
__device__ __align__(256) __nv_bfloat16 g_wo_hi[CC * CI];
__device__ __align__(256) __nv_bfloat16 g_wo_lo[CC * CI];
__device__ __align__(256) __nv_bfloat16 g_th_hi[BB * NN * CI]; // theta [b][n][o]
__device__ __align__(256) __nv_bfloat16 g_th_lo[BB * NN * CI];
__device__ __align__(256) __nv_bfloat16 g_ph_hi[BB * NN * CI]; // phi   [b][n][o]
__device__ __align__(256) __nv_bfloat16 g_ph_lo[BB * NN * CI];
__device__ __align__(256) __half       g_g16 [BB * CI * NN];   // g     [b][o][n] fp16
__device__ __align__(256) __nv_bfloat16 g_y_hi[BB * NN * CI];  // y     [b][n][o]
__device__ __align__(256) __nv_bfloat16 g_y_lo[BB * NN * CI];

// ---------------- PTX helpers ----------------
__device__ __forceinline__ void cp16(u32 dst, const void* src) {
    asm volatile("cp.async.ca.shared.global [%0], [%1], 16;" :: "r"(dst), "l"(src));
}
#define CP_COMMIT() asm volatile("cp.async.commit_group;" ::: "memory")
#define CP_WAIT0()  asm volatile("cp.async.wait_group 0;" ::: "memory")

__device__ __forceinline__ u32 smem_u32(const void* p) {
    u32 a;
    asm("{ .reg .u64 t; cvta.to.shared.u64 t, %1; cvt.u32.u64 %0, t; }" : "=r"(a) : "l"(p));
    return a;
}
__device__ __forceinline__ void mma_bf16(float c[4], const u32 a[4], const u32 b[2]) {
    asm volatile("mma.sync.aligned.m16n8k16.row.col.f32.bf16.bf16.f32 "
                 "{%0,%1,%2,%3}, {%4,%5,%6,%7}, {%8,%9}, {%0,%1,%2,%3};"
                 : "+f"(c[0]), "+f"(c[1]), "+f"(c[2]), "+f"(c[3])
                 : "r"(a[0]), "r"(a[1]), "r"(a[2]), "r"(a[3]), "r"(b[0]), "r"(b[1]));
}
__device__ __forceinline__ void mma_f16(float c[4], const u32 a[4], const u32 b[2]) {
    asm volatile("mma.sync.aligned.m16n8k16.row.col.f32.f16.f16.f32 "
                 "{%0,%1,%2,%3}, {%4,%5,%6,%7}, {%8,%9}, {%0,%1,%2,%3};"
                 : "+f"(c[0]), "+f"(c[1]), "+f"(c[2]), "+f"(c[3])
                 : "r"(a[0]), "r"(a[1]), "r"(a[2]), "r"(a[3]), "r"(b[0]), "r"(b[1]));
}
__device__ __forceinline__ u32 pack_bf2(float a, float b) {
    u32 ra = (u32)__bfloat16_as_ushort(__float2bfloat16_rn(a));
    u32 rb = (u32)__bfloat16_as_ushort(__float2bfloat16_rn(b));
    return ra | (rb << 16);
}
__device__ __forceinline__ float bf_hi(float v) {
    return __bfloat162float(__float2bfloat16_rn(v));
}
__device__ __forceinline__ u32 pack_h2(float a, float b) {
    __half2 h = __floats2half2_rn(a, b);
    return *(u32*)&h;
}

// ===========================================================================
// Kernel 0a: transpose + split x [b][c][n] fp32 -> x_t hi/lo [b][n][c] bf16
// ===========================================================================
__global__ __launch_bounds__(256) void xsplit_kernel(const float* __restrict__ x)
{
    __shared__ float t[32][33];
    int b  = blockIdx.z;
    int n0 = blockIdx.x * 32;
    int c0 = blockIdx.y * 32;
    int tx = threadIdx.x & 31, ty = threadIdx.x >> 5;  // ty 0..7
    const float* xb = x + (size_t)b * CC * NN;
    #pragma unroll
    for (int j = 0; j < 4; j++)
        t[ty + 8 * j][tx] = xb[(size_t)(c0 + ty + 8 * j) * NN + n0 + tx];
    __syncthreads();
    size_t base = (size_t)b * NN * CC;
    #pragma unroll
    for (int j = 0; j < 4; j++) {
        int n = n0 + ty + 8 * j;
        float v = t[tx][ty + 8 * j];
        float h = bf_hi(v);
        g_xt_hi[base + (size_t)n * CC + c0 + tx] = __float2bfloat16_rn(h);
        g_xt_lo[base + (size_t)n * CC + c0 + tx] = __float2bfloat16_rn(v - h);
    }
}

// ===========================================================================
// Kernel 0b: split the 4 weight matrices into bf16 hi/lo
// ===========================================================================
__global__ __launch_bounds__(256) void wsplit_kernel(
    const float* __restrict__ wt, const float* __restrict__ wp,
    const float* __restrict__ wg, const float* __restrict__ wo)
{
    int idx = blockIdx.x * 256 + threadIdx.x;          // 0..131071
    int which = blockIdx.y;
    const float* src = (which == 0) ? wt : (which == 1) ? wp : (which == 2) ? wg : wo;
    __nv_bfloat16* dh = (which == 0) ? g_wt_hi : (which == 1) ? g_wp_hi : (which == 2) ? g_wg_hi : g_wo_hi;
    __nv_bfloat16* dl = (which == 0) ? g_wt_lo : (which == 1) ? g_wp_lo : (which == 2) ? g_wg_lo : g_wo_lo;
    float v = src[idx];
    float h = bf_hi(v);
    dh[idx] = __float2bfloat16_rn(h);
    dl[idx] = __float2bfloat16_rn(v - h);
}

// ---- shared stage geometry for the mma GEMM kernels ----
// stage = A_hi | A_lo | B_hi | B_lo, each [128 rows][64 k] bf16, pitch 144 B
#define ST_ALO 18432
#define ST_BHI 36864
#define ST_BLO 55296
#define ST_SZ  73728
#define GEMM_SMEM (2 * ST_SZ)

// ===========================================================================
// Kernel 1: projections via mma.sync, 3-pass bf16 hi/lo.
// blockIdx.x: 0..191 -> mat(0 theta,1 phi,2 g), blockIdx.y = b
// ===========================================================================
__global__ __launch_bounds__(256, 1) void proj_mma(
    const float* __restrict__ bt, const float* __restrict__ bp,
    const float* __restrict__ bg)
{
    extern __shared__ __align__(1024) char sm[];
    u32 dyn = smem_u32(sm);
    int id = blockIdx.x, b = blockIdx.y;
    int mat = id >> 6, sub = id & 63;
    int tid = threadIdx.x, lane = tid & 31, wid = tid >> 5;
    int gid = lane >> 2, tig = lane & 3;

    const __nv_bfloat16 *Ahi, *Alo, *Bhi, *Blo;
    const float* bias;
    int mt, ot;   // row tile, col tile
    if (mat < 2) {
        mt = sub & 31; ot = sub >> 5;
        Ahi = g_xt_hi + (size_t)b * NN * CC + (size_t)(mt * 128) * CC;
        Alo = g_xt_lo + (size_t)b * NN * CC + (size_t)(mt * 128) * CC;
        Bhi = (mat ? g_wp_hi : g_wt_hi) + (size_t)(ot * 128) * CC;
        Blo = (mat ? g_wp_lo : g_wt_lo) + (size_t)(ot * 128) * CC;
        bias = mat ? bp : bt;
    } else {
        mt = sub >> 5; ot = sub & 31;   // mt over o (2), ot over n (32)
        Ahi = g_wg_hi + (size_t)(mt * 128) * CC;
        Alo = g_wg_lo + (size_t)(mt * 128) * CC;
        Bhi = g_xt_hi + (size_t)b * NN * CC + (size_t)(ot * 128) * CC;
        Blo = g_xt_lo + (size_t)b * NN * CC + (size_t)(ot * 128) * CC;
        bias = bg;
    }

    auto stage_load = [&](int kc, int buf) {
        u32 base = dyn + buf * ST_SZ;
        #pragma unroll
        for (int i = 0; i < 4; i++) {
            int idx2 = tid + i * 256;
            int r = idx2 >> 3, c = idx2 & 7;
            u32 o = r * 144 + c * 16;
            cp16(base + o,          Ahi + (size_t)r * CC + kc + c * 8);
            cp16(base + ST_ALO + o, Alo + (size_t)r * CC + kc + c * 8);
            cp16(base + ST_BHI + o, Bhi + (size_t)r * CC + kc + c * 8);
            cp16(base + ST_BLO + o, Blo + (size_t)r * CC + kc + c * 8);
        }
    };

    float acc[16][4];
    #pragma unroll
    for (int nb = 0; nb < 16; nb++)
        #pragma unroll
        for (int j = 0; j < 4; j++) acc[nb][j] = 0.f;

    stage_load(0, 0);
    CP_COMMIT();

    int m0 = wid * 16;
    for (int kc8 = 0; kc8 < 8; kc8++) {
        CP_WAIT0();
        __syncthreads();
        if (kc8 < 7) { stage_load((kc8 + 1) * 64, (kc8 + 1) & 1); CP_COMMIT(); }

        u32 sb = (kc8 & 1) * ST_SZ;
        #pragma unroll
        for (int ks = 0; ks < 4; ks++) {
            u32 a0 = sb + (m0 + gid) * 144 + (ks * 16 + 2 * tig) * 2;
            u32 ah[4], al[4];
            ah[0] = *(const u32*)(sm + a0);
            ah[1] = *(const u32*)(sm + a0 + 8 * 144);
            ah[2] = *(const u32*)(sm + a0 + 16);
            ah[3] = *(const u32*)(sm + a0 + 8 * 144 + 16);
            al[0] = *(const u32*)(sm + a0 + ST_ALO);
            al[1] = *(const u32*)(sm + a0 + ST_ALO + 8 * 144);
            al[2] = *(const u32*)(sm + a0 + ST_ALO + 16);
            al[3] = *(const u32*)(sm + a0 + ST_ALO + 8 * 144 + 16);
            #pragma unroll
            for (int nb = 0; nb < 16; nb++) {
                u32 bo = sb + ST_BHI + (nb * 8 + gid) * 144 + (ks * 16 + 2 * tig) * 2;
                u32 bh[2], bl[2];
                bh[0] = *(const u32*)(sm + bo);
                bh[1] = *(const u32*)(sm + bo + 16);
                bl[0] = *(const u32*)(sm + bo + (ST_BLO - ST_BHI));
                bl[1] = *(const u32*)(sm + bo + (ST_BLO - ST_BHI) + 16);
                mma_bf16(acc[nb], ah, bh);
                mma_bf16(acc[nb], ah, bl);
                mma_bf16(acc[nb], al, bh);
            }
        }
    }

    // ---- epilogue ----
    if (mat < 2) {
        // rows = n, cols = o; outputs [n][o] hi/lo bf16
        __nv_bfloat16* oh = (mat ? g_ph_hi : g_th_hi) + (size_t)b * NN * CI;
        __nv_bfloat16* ol = (mat ? g_ph_lo : g_th_lo) + (size_t)b * NN * CI;
        int nrow = mt * 128 + m0 + gid;
        #pragma unroll
        for (int nb = 0; nb < 16; nb++) {
            int o = ot * 128 + nb * 8 + 2 * tig;
            float b0 = bias[o], b1 = bias[o + 1];
            float v0 = acc[nb][0] + b0, v1 = acc[nb][1] + b1;
            float v2 = acc[nb][2] + b0, v3 = acc[nb][3] + b1;
            float h0 = bf_hi(v0), h1 = bf_hi(v1), h2 = bf_hi(v2), h3 = bf_hi(v3);
            *(u32*)(oh + (size_t)nrow * CI + o)       = pack_bf2(h0, h1);
            *(u32*)(ol + (size_t)nrow * CI + o)       = pack_bf2(v0 - h0, v1 - h1);
            *(u32*)(oh + (size_t)(nrow + 8) * CI + o) = pack_bf2(h2, h3);
            *(u32*)(ol + (size_t)(nrow + 8) * CI + o) = pack_bf2(v2 - h2, v3 - h3);
        }
    } else {
        // rows = o, cols = n; output g fp16 [o][n]
        __half* gb = g_g16 + (size_t)b * CI * NN;
        int orow = mt * 128 + m0 + gid;
        float b0 = bias[orow], b8 = bias[orow + 8];
        #pragma unroll
        for (int nb = 0; nb < 16; nb++) {
            int n = ot * 128 + nb * 8 + 2 * tig;
            *(u32*)(gb + (size_t)orow * NN + n)       = pack_h2(acc[nb][0] + b0, acc[nb][1] + b0);
            *(u32*)(gb + (size_t)(orow + 8) * NN + n) = pack_h2(acc[nb][2] + b8, acc[nb][3] + b8);
        }
    }
}

// ---- attention smem layout (unchanged from R11) ----
#define TH_HI_OFF 0
#define TH_LO_OFF 67584
#define PH_OFF    135168
#define PH_BUF    18432
#define PH_LO     9216
#define P_OFF     172032
#define G_OFF     190464
#define DYN_SMEM  227328

// ===========================================================================
// Kernel 2: mma.sync flash attention (R11, epilogue now writes y hi/lo bf16)
// ===========================================================================
__global__ __launch_bounds__(256, 1) void attn_kernel()
{
    extern __shared__ __align__(1024) char dsm[];
    u32 dyn = smem_u32(dsm);

    int b    = blockIdx.y;
    int q0   = blockIdx.x * QT;
    int tid  = threadIdx.x;
    int lane = tid & 31;
    int wid  = tid >> 5;
    int q0w  = wid * 16;
    int gid  = lane >> 2;
    int tig  = lane & 3;

    const __nv_bfloat16* th_hi = g_th_hi + (size_t)b * NN * CI;
    const __nv_bfloat16* th_lo = g_th_lo + (size_t)b * NN * CI;
    const __nv_bfloat16* ph_hi = g_ph_hi + (size_t)b * NN * CI;
    const __nv_bfloat16* ph_lo = g_ph_lo + (size_t)b * NN * CI;
    const __half*        gg    = g_g16  + (size_t)b * CI * NN;

    for (int idx = tid; idx < 4096; idx += 256) {
        int r = idx >> 5, c = idx & 31;
        *(uint4*)(dsm + TH_HI_OFF + r * 528 + c * 16) =
            *(const uint4*)(th_hi + (size_t)(q0 + r) * CI + c * 8);
        *(uint4*)(dsm + TH_LO_OFF + r * 528 + c * 16) =
            *(const uint4*)(th_lo + (size_t)(q0 + r) * CI + c * 8);
    }

    auto issue_phi = [&](int t_, int oc_, int buf) {
        #pragma unroll
        for (int i = 0; i < 2; i++) {
            int idx = tid + i * 256;
            int r = idx >> 3, c = idx & 7;
            u32 d = dyn + PH_OFF + buf * PH_BUF + r * 144 + c * 16;
            cp16(d, ph_hi + (size_t)(t_ * 64 + r) * CI + oc_ * 64 + c * 8);
            cp16(d + PH_LO, ph_lo + (size_t)(t_ * 64 + r) * CI + oc_ * 64 + c * 8);
        }
    };
    auto issue_g = [&](int t_) {
        #pragma unroll
        for (int i = 0; i < 8; i++) {
            int idx = tid + i * 256;
            int r = idx >> 3, c = idx & 7;
            cp16(dyn + G_OFF + r * 144 + c * 16,
                 gg + (size_t)r * NN + t_ * 64 + c * 8);
        }
    };

    issue_phi(0, 0, 0);
    CP_COMMIT();

    float M0 = -1e30f, M1 = -1e30f, l0 = 0.f, l1 = 0.f;
    float yacc[32][4];
    #pragma unroll
    for (int k = 0; k < 32; k++)
        #pragma unroll
        for (int j = 0; j < 4; j++) yacc[k][j] = 0.f;

    for (int t = 0; t < 64; t++) {
        float sf[8][4];
        #pragma unroll
        for (int nb = 0; nb < 8; nb++)
            #pragma unroll
            for (int j = 0; j < 4; j++) sf[nb][j] = 0.f;

        for (int oc = 0; oc < 4; oc++) {
            CP_WAIT0();
            __syncthreads();
            if (oc < 3) issue_phi(t, oc + 1, (oc + 1) & 1);
            else { issue_g(t); if (t < 63) issue_phi(t + 1, 0, 0); }
            CP_COMMIT();

            u32 phb = dyn + PH_OFF + (oc & 1) * PH_BUF;
            #pragma unroll
            for (int ks = 0; ks < 4; ks++) {
                u32 acol = (oc * 64 + ks * 16 + 2 * tig) * 2;
                u32 a0 = TH_HI_OFF + (q0w + gid) * 528 + acol;
                u32 ah[4], al[4];
                ah[0] = *(const u32*)(dsm + a0);
                ah[1] = *(const u32*)(dsm + a0 + 8 * 528);
                ah[2] = *(const u32*)(dsm + a0 + 16);
                ah[3] = *(const u32*)(dsm + a0 + 8 * 528 + 16);
                al[0] = *(const u32*)(dsm + a0 + (TH_LO_OFF - TH_HI_OFF));
                al[1] = *(const u32*)(dsm + a0 + (TH_LO_OFF - TH_HI_OFF) + 8 * 528);
                al[2] = *(const u32*)(dsm + a0 + (TH_LO_OFF - TH_HI_OFF) + 16);
                al[3] = *(const u32*)(dsm + a0 + (TH_LO_OFF - TH_HI_OFF) + 8 * 528 + 16);
                #pragma unroll
                for (int nb = 0; nb < 8; nb++) {
                    u32 boff = (phb - dyn) + (nb * 8 + gid) * 144 + (ks * 16 + 2 * tig) * 2;
                    u32 bh[2], bl[2];
                    bh[0] = *(const u32*)(dsm + boff);
                    bh[1] = *(const u32*)(dsm + boff + 16);
                    bl[0] = *(const u32*)(dsm + boff + PH_LO);
                    bl[1] = *(const u32*)(dsm + boff + PH_LO + 16);
                    mma_bf16(sf[nb], ah, bh);
                    mma_bf16(sf[nb], ah, bl);
                    mma_bf16(sf[nb], al, bh);
                }
            }
        }

        float mx0 = -1e30f, mx1 = -1e30f;
        #pragma unroll
        for (int nb = 0; nb < 8; nb++) {
            mx0 = fmaxf(mx0, fmaxf(sf[nb][0], sf[nb][1]));
            mx1 = fmaxf(mx1, fmaxf(sf[nb][2], sf[nb][3]));
        }
        mx0 = fmaxf(mx0, __shfl_xor_sync(0xffffffffu, mx0, 1));
        mx0 = fmaxf(mx0, __shfl_xor_sync(0xffffffffu, mx0, 2));
        mx1 = fmaxf(mx1, __shfl_xor_sync(0xffffffffu, mx1, 1));
        mx1 = fmaxf(mx1, __shfl_xor_sync(0xffffffffu, mx1, 2));

        float Mn0 = fmaxf(M0, mx0), Mn1 = fmaxf(M1, mx1);
        if (Mn0 > M0 || Mn1 > M1) {
            float sc0 = __expf(M0 - Mn0), sc1 = __expf(M1 - Mn1);
            M0 = Mn0; M1 = Mn1;
            l0 *= sc0; l1 *= sc1;
            #pragma unroll
            for (int k = 0; k < 32; k++) {
                yacc[k][0] *= sc0; yacc[k][1] *= sc0;
                yacc[k][2] *= sc1; yacc[k][3] *= sc1;
            }
        }

        u32 p0off = P_OFF + (q0w + gid) * 144 + 2 * tig * 2;
        #pragma unroll
        for (int nb = 0; nb < 8; nb++) {
            float p0 = __expf(sf[nb][0] - M0);
            float p1 = __expf(sf[nb][1] - M0);
            float p2 = __expf(sf[nb][2] - M1);
            float p3 = __expf(sf[nb][3] - M1);
            l0 += p0 + p1;
            l1 += p2 + p3;
            *(u32*)(dsm + p0off + nb * 16)           = pack_h2(p0, p1);
            *(u32*)(dsm + p0off + nb * 16 + 8 * 144) = pack_h2(p2, p3);
        }

        CP_WAIT0();
        __syncthreads();

        #pragma unroll
        for (int ks = 0; ks < 4; ks++) {
            u32 pa = P_OFF + (q0w + gid) * 144 + (ks * 16 + 2 * tig) * 2;
            u32 ap[4];
            ap[0] = *(const u32*)(dsm + pa);
            ap[1] = *(const u32*)(dsm + pa + 8 * 144);
            ap[2] = *(const u32*)(dsm + pa + 16);
            ap[3] = *(const u32*)(dsm + pa + 8 * 144 + 16);
            #pragma unroll
            for (int nt = 0; nt < 32; nt++) {
                u32 gb = G_OFF + (nt * 8 + gid) * 144 + (ks * 16 + 2 * tig) * 2;
                u32 bg[2];
                bg[0] = *(const u32*)(dsm + gb);
                bg[1] = *(const u32*)(dsm + gb + 16);
                mma_f16(yacc[nt], ap, bg);
            }
        }
        __syncthreads();
    }

    // epilogue: normalize, split hi/lo, store bf16
    l0 += __shfl_xor_sync(0xffffffffu, l0, 1);
    l0 += __shfl_xor_sync(0xffffffffu, l0, 2);
    l1 += __shfl_xor_sync(0xffffffffu, l1, 1);
    l1 += __shfl_xor_sync(0xffffffffu, l1, 2);
    float inv0 = 1.f / l0, inv1 = 1.f / l1;

    int r0 = q0 + q0w + gid;
    __nv_bfloat16* yh = g_y_hi + (size_t)b * NN * CI;
    __nv_bfloat16* yl = g_y_lo + (size_t)b * NN * CI;
    #pragma unroll
    for (int nt = 0; nt < 32; nt++) {
        int o = nt * 8 + 2 * tig;
        float v0 = yacc[nt][0] * inv0, v1 = yacc[nt][1] * inv0;
        float v2 = yacc[nt][2] * inv1, v3 = yacc[nt][3] * inv1;
        float h0 = bf_hi(v0), h1 = bf_hi(v1), h2 = bf_hi(v2), h3 = bf_hi(v3);
        *(u32*)(yh + (size_t)r0 * CI + o)       = pack_bf2(h0, h1);
        *(u32*)(yl + (size_t)r0 * CI + o)       = pack_bf2(v0 - h0, v1 - h1);
        *(u32*)(yh + (size_t)(r0 + 8) * CI + o) = pack_bf2(h2, h3);
        *(u32*)(yl + (size_t)(r0 + 8) * CI + o) = pack_bf2(v2 - h2, v3 - h3);
    }
}

// ===========================================================================
// Kernel 3: out = w_out.y + b + x via mma.sync 3-pass.
// blockIdx.x: ct(4) * nt(32) = 128, blockIdx.y = b
// ===========================================================================
__global__ __launch_bounds__(256, 1) void out_mma(
    const float* __restrict__ x, const float* __restrict__ bo,
    float* __restrict__ out)
{
    extern __shared__ __align__(1024) char sm[];
    u32 dyn = smem_u32(sm);
    int id = blockIdx.x, b = blockIdx.y;
    int ct = id >> 5, nt = id & 31;
    int tid = threadIdx.x, lane = tid & 31, wid = tid >> 5;
    int gid = lane >> 2, tig = lane & 3;

    const __nv_bfloat16* Ahi = g_wo_hi + (size_t)(ct * 128) * CI;
    const __nv_bfloat16* Alo = g_wo_lo + (size_t)(ct * 128) * CI;
    const __nv_bfloat16* Bhi = g_y_hi + (size_t)b * NN * CI + (size_t)(nt * 128) * CI;
    const __nv_bfloat16* Blo = g_y_lo + (size_t)b * NN * CI + (size_t)(nt * 128) * CI;

    auto stage_load = [&](int kc, int buf) {
        u32 base = dyn + buf * ST_SZ;
        #pragma unroll
        for (int i = 0; i < 4; i++) {
            int idx2 = tid + i * 256;
            int r = idx2 >> 3, c = idx2 & 7;
            u32 o = r * 144 + c * 16;
            cp16(base + o,          Ahi + (size_t)r * CI + kc + c * 8);
            cp16(base + ST_ALO + o, Alo + (size_t)r * CI + kc + c * 8);
            cp16(base + ST_BHI + o, Bhi + (size_t)r * CI + kc + c * 8);
            cp16(base + ST_BLO + o, Blo + (size_t)r * CI + kc + c * 8);
        }
    };

    float acc[16][4];
    #pragma unroll
    for (int nb = 0; nb < 16; nb++)
        #pragma unroll
        for (int j = 0; j < 4; j++) acc[nb][j] = 0.f;

    stage_load(0, 0);
    CP_COMMIT();

    int m0 = wid * 16;
    for (int kc4 = 0; kc4 < 4; kc4++) {
        CP_WAIT0();
        __syncthreads();
        if (kc4 < 3) { stage_load((kc4 + 1) * 64, (kc4 + 1) & 1); CP_COMMIT(); }

        u32 sb = (kc4 & 1) * ST_SZ;
        #pragma unroll
        for (int ks = 0; ks < 4; ks++) {
            u32 a0 = sb + (m0 + gid) * 144 + (ks * 16 + 2 * tig) * 2;
            u32 ah[4], al[4];
            ah[0] = *(const u32*)(sm + a0);
            ah[1] = *(const u32*)(sm + a0 + 8 * 144);
            ah[2] = *(const u32*)(sm + a0 + 16);
            ah[3] = *(const u32*)(sm + a0 + 8 * 144 + 16);
            al[0] = *(const u32*)(sm + a0 + ST_ALO);
            al[1] = *(const u32*)(sm + a0 + ST_ALO + 8 * 144);
            al[2] = *(const u32*)(sm + a0 + ST_ALO + 16);
            al[3] = *(const u32*)(sm + a0 + ST_ALO + 8 * 144 + 16);
            #pragma unroll
            for (int nb = 0; nb < 16; nb++) {
                u32 bo2 = sb + ST_BHI + (nb * 8 + gid) * 144 + (ks * 16 + 2 * tig) * 2;
                u32 bh[2], bl[2];
                bh[0] = *(const u32*)(sm + bo2);
                bh[1] = *(const u32*)(sm + bo2 + 16);
                bl[0] = *(const u32*)(sm + bo2 + (ST_BLO - ST_BHI));
                bl[1] = *(const u32*)(sm + bo2 + (ST_BLO - ST_BHI) + 16);
                mma_bf16(acc[nb], ah, bh);
                mma_bf16(acc[nb], ah, bl);
                mma_bf16(acc[nb], al, bh);
            }
        }
    }

    // epilogue: + bias + residual, fp32 out [c][n]
    const float* xb = x + (size_t)b * CC * NN;
    float* ob = out + (size_t)b * CC * NN;
    int c0r = ct * 128 + m0 + gid;
    float bc0 = bo[c0r], bc8 = bo[c0r + 8];
    #pragma unroll
    for (int nb = 0; nb < 16; nb++) {
        int n = nt * 128 + nb * 8 + 2 * tig;
        float2 xv0 = *(const float2*)(xb + (size_t)c0r * NN + n);
        float2 xv8 = *(const float2*)(xb + (size_t)(c0r + 8) * NN + n);
        float2 v0 = { acc[nb][0] + bc0 + xv0.x, acc[nb][1] + bc0 + xv0.y };
        float2 v8 = { acc[nb][2] + bc8 + xv8.x, acc[nb][3] + bc8 + xv8.y };
        *(float2*)(ob + (size_t)c0r * NN + n)       = v0;
        *(float2*)(ob + (size_t)(c0r + 8) * NN + n) = v8;
    }
}

extern "C" void kernel_launch(void* const* d_in, const int* in_sizes, int n_in,
                              void* d_out, int out_size)
{
    const float* x  = (const float*)d_in[0];
    const float* wt = (const float*)d_in[1];
    const float* bt = (const float*)d_in[2];
    const float* wp = (const float*)d_in[3];
    const float* bp = (const float*)d_in[4];
    const float* wg = (const float*)d_in[5];
    const float* bg = (const float*)d_in[6];
    const float* wo = (const float*)d_in[7];
    const float* bo = (const float*)d_in[8];
    float* out = (float*)d_out;

    cudaFuncSetAttribute(attn_kernel, cudaFuncAttributeMaxDynamicSharedMemorySize, DYN_SMEM);
    cudaFuncSetAttribute(proj_mma, cudaFuncAttributeMaxDynamicSharedMemorySize, GEMM_SMEM);
    cudaFuncSetAttribute(out_mma, cudaFuncAttributeMaxDynamicSharedMemorySize, GEMM_SMEM);

    xsplit_kernel<<<dim3(NN / 32, CC / 32, BB), 256>>>(x);
    wsplit_kernel<<<dim3(512, 4), 256>>>(wt, wp, wg, wo);

    proj_mma<<<dim3(192, BB), 256, GEMM_SMEM>>>(bt, bp, bg);

    attn_kernel<<<dim3(NN / QT, BB), 256, DYN_SMEM>>>();

    out_mma<<<dim3(128, BB), 256, GEMM_SMEM>>>(x, bo, out);
}